// round 13
// baseline (speedup 1.0000x reference)
#include <cuda_runtime.h>
#include <cstdint>

#define BN 512
#define NSTEPS 100

// ---------------- persistent device state (allocation-free scratch) ----------------
__device__ uint32_t g_opm_all [NSTEPS][BN * 196];   // pool1 spike masks per step (bit ci)
__device__ uint32_t g_op2m_all[NSTEPS][BN][2][40];  // pool2 spike masks per step (k=cb*1225+w*32+j)
__device__ float    g_tf0 [BN * 200];               // fc0 total spike count (ONLY output that matters)
__device__ float    g_w2t [2 * 500 * 26];           // conv2 weights pre-transposed [cb][kk*20+ci][ch pad26]
__device__ float    g_wf0T[2450 * 200];             // wf0 transposed [k][n]

// ---------------- Threefry-2x32, 20 rounds (matches JAX exactly) ----------------
__host__ __device__ __forceinline__ void tf2x32(uint32_t k0, uint32_t k1,
                                                uint32_t x0, uint32_t x1,
                                                uint32_t& o0, uint32_t& o1) {
    uint32_t k2 = k0 ^ k1 ^ 0x1BD11BDAu;
    x0 += k0; x1 += k1;
#define TFR(r) { x0 += x1; x1 = (x1 << (r)) | (x1 >> (32 - (r))); x1 ^= x0; }
    TFR(13) TFR(15) TFR(26) TFR(6)   x0 += k1; x1 += k2 + 1u;
    TFR(17) TFR(29) TFR(16) TFR(24)  x0 += k2; x1 += k0 + 2u;
    TFR(13) TFR(15) TFR(26) TFR(6)   x0 += k0; x1 += k1 + 3u;
    TFR(17) TFR(29) TFR(16) TFR(24)  x0 += k1; x1 += k2 + 4u;
    TFR(13) TFR(15) TFR(26) TFR(6)   x0 += k2; x1 += k0 + 5u;
#undef TFR
    o0 = x0; o1 = x1;
}

// ---------------- one-time prep: transpose w2 and wf0 ----------------
__global__ void k_prep(const float* __restrict__ w2, const float* __restrict__ wf0) {
    int i = blockIdx.x * blockDim.x + threadIdx.x;
    if (i < 2 * 500 * 26) {
        int ch = i % 26, rem = i / 26, kkci = rem % 500, cb = rem / 500;
        int kk = kkci / 20, ci = kkci % 20;
        g_w2t[i] = (ch < 25) ? w2[(cb * 25 + ch) * 500 + ci * 25 + kk] : 0.f;
    }
    int j = i - 2 * 500 * 26;
    if (j >= 0 && j < 2450 * 200) {
        int n = j % 200, k = j / 200;
        g_wf0T[j] = wf0[n * 2450 + k];
    }
}

// ---------------- conv1, ALL steps: membranes live in smem for the whole run ----------------
// block = image, 224 threads (196 compute). Per-step math byte-identical to round 10.
#define C1_SMEM ((15680 + 3920 + 1024 + 784 + 500) * 4)   // m1, m1s, sin, img, sw
__global__ __launch_bounds__(224, 2) void k_conv1_all(const float* __restrict__ in,
                                                      const float* __restrict__ w1) {
    extern __shared__ float dynf[];
    float* m1   = dynf;                  // 20*784
    float* m1s  = dynf + 15680;          // 20*196
    float* sin_ = dynf + 19600;          // 32*32 padded spikes
    float* img  = dynf + 20624;          // 784 raw input
    float* sw   = dynf + 21408;          // 20*25 weights
    int b = blockIdx.x;
    int t = threadIdx.x;
    for (int i = t; i < 15680; i += 224) m1[i] = 0.f;
    for (int i = t; i < 3920;  i += 224) m1s[i] = 0.f;
    for (int i = t; i < 1024;  i += 224) sin_[i] = 0.f;
    for (int i = t; i < 784;   i += 224) img[i] = in[b * 784 + i];
    for (int i = t; i < 500;   i += 224) sw[i] = w1[i];
    __syncthreads();

    for (int tt = 0; tt < NSTEPS; tt++) {
        // per-step key: JAX partitionable split — key_t = threefry((0,42),(0,tt))
        uint32_t kk0, kk1;
        tf2x32(0u, 42u, 0u, (uint32_t)tt, kk0, kk1);
        for (int i = t; i < 784; i += 224) {
            uint32_t o0, o1;
            tf2x32(kk0, kk1, 0u, (uint32_t)(b * 784 + i), o0, o1);
            uint32_t bits = o0 ^ o1;
            float u = __uint_as_float((bits >> 9) | 0x3f800000u) - 1.0f;
            float v = img[i];
            float sgn = (v > 0.f) ? 1.f : ((v < 0.f) ? -1.f : 0.f);
            sin_[(2 + i / 28) * 32 + 2 + i % 28] = (fabsf(v) * 0.5f > u) ? sgn : 0.f;
        }
        __syncthreads();

        if (t < 196) {
            int py = t / 14, px = t % 14;
            int r0 = 2 * py, c0 = 2 * px;
            float p[6][6];
#pragma unroll
            for (int r = 0; r < 6; r++)
#pragma unroll
                for (int c = 0; c < 6; c++) p[r][c] = sin_[(r0 + r) * 32 + c0 + c];

            uint32_t mask = 0u;
            for (int ch = 0; ch < 20; ch++) {
                const float* w = &sw[ch * 25];
                float a00 = 0.f, a01 = 0.f, a10 = 0.f, a11 = 0.f;
#pragma unroll
                for (int ky = 0; ky < 5; ky++)
#pragma unroll
                    for (int kx = 0; kx < 5; kx++) {
                        float wv = w[ky * 5 + kx];
                        a00 = __fmaf_rn(p[ky][kx],         wv, a00);
                        a01 = __fmaf_rn(p[ky][kx + 1],     wv, a01);
                        a10 = __fmaf_rn(p[ky + 1][kx],     wv, a10);
                        a11 = __fmaf_rn(p[ky + 1][kx + 1], wv, a11);
                    }
                int mb = ch * 784;
                int i00 = r0 * 28 + c0;
                float m00 = m1[mb + i00]      + a00;
                float m01 = m1[mb + i00 + 1]  + a01;
                float m10 = m1[mb + i00 + 28] + a10;
                float m11 = m1[mb + i00 + 29] + a11;
                float f00 = (m00 > 1.f) ? 1.f : 0.f; m1[mb + i00]      = (m00 > 1.f) ? 0.f : m00;
                float f01 = (m01 > 1.f) ? 1.f : 0.f; m1[mb + i00 + 1]  = (m01 > 1.f) ? 0.f : m01;
                float f10 = (m10 > 1.f) ? 1.f : 0.f; m1[mb + i00 + 28] = (m10 > 1.f) ? 0.f : m10;
                float f11 = (m11 > 1.f) ? 1.f : 0.f; m1[mb + i00 + 29] = (m11 > 1.f) ? 0.f : m11;
                int pi = ch * 196 + t;
                float ms = m1s[pi] + 0.25f * (f00 + f01 + f10 + f11);
                if (ms > 0.75f) { mask |= (1u << ch); m1s[pi] = 0.f; }
                else            { m1s[pi] = ms; }
            }
            g_opm_all[tt][b * 196 + t] = mask;
        }
        __syncthreads();   // sin_ reused next step
    }
}

// ---------------- conv2, ALL steps: weights staged once, membranes in smem ----------------
// block = (image, cb); 256 threads = 5 cogs x 49 positions, 5 ch/thread.
// Ping-pong mask buffers prefetch step tt+1 during compute of tt.
#define C2_SMEM ((13000 + 4900 + 1225 + 2 * 324 + 2 * 40) * 4)
__global__ __launch_bounds__(256, 2) void k_conv2_all() {
    extern __shared__ float dynf[];
    float*    swt    = dynf;                            // 25*500 weights [kk*20+ci]*26+ch... (kk*520+ci*26+ch)
    float*    m2     = dynf + 13000;                    // 25*196
    float*    m2s    = dynf + 17900;                    // 25*49
    uint32_t* smA    = (uint32_t*)(dynf + 19125);       // 2 x 324 mask buffers
    uint32_t* smaskA = (uint32_t*)(dynf + 19125 + 648); // 2 x 40 output masks
    int b  = blockIdx.x;
    int cb = blockIdx.y;
    int t = threadIdx.x;
    {
        const float4* src = (const float4*)(g_w2t + cb * 13000);
        float4* dst = (float4*)swt;
        for (int i = t; i < 3250; i += 256) dst[i] = src[i];
    }
    for (int i = t; i < 4900; i += 256) m2[i] = 0.f;
    for (int i = t; i < 1225; i += 256) m2s[i] = 0.f;
    // preload step 0 masks into buffer 0
    for (int i = t; i < 324; i += 256) {
        int rr = i / 18 - 2, cc = i % 18 - 2;
        smA[i] = (rr >= 0 && rr < 14 && cc >= 0 && cc < 14) ? g_opm_all[0][b * 196 + rr * 14 + cc] : 0u;
    }
    if (t < 40) smaskA[t] = 0u;
    __syncthreads();

    for (int tt = 0; tt < NSTEPS; tt++) {
        int cur = tt & 1;
        uint32_t* sm    = smA + cur * 324;
        uint32_t* smask = smaskA + cur * 40;
        // prefetch step tt+1 into the other buffer (overlaps with compute below)
        if (tt + 1 < NSTEPS) {
            uint32_t* smn = smA + (1 - cur) * 324;
            for (int i = t; i < 324; i += 256) {
                int rr = i / 18 - 2, cc = i % 18 - 2;
                smn[i] = (rr >= 0 && rr < 14 && cc >= 0 && cc < 14) ? g_opm_all[tt + 1][b * 196 + rr * 14 + cc] : 0u;
            }
            if (t < 40) smaskA[(1 - cur) * 40 + t] = 0u;
        }

        if (t < 245) {
            int cog = t / 49, q = t % 49;
            int py = q / 7, px = q % 7;
            int r0 = 2 * py, c0 = 2 * px;
            float acc[5][4] = {};
#pragma unroll 1
            for (int ky = 0; ky < 5; ky++) {
                const uint32_t* mr0 = &sm[(r0 + ky) * 18 + c0];
                const uint32_t* mr1 = mr0 + 18;
#pragma unroll 1
                for (int kx = 0; kx < 5; kx++) {
                    uint32_t m0 = mr0[kx], m1 = mr0[kx + 1];
                    uint32_t m2w = mr1[kx], m3 = mr1[kx + 1];
                    const float* wk = &swt[(ky * 5 + kx) * 20 * 26 + cog * 5];
                    while (m0) {
                        int ci = __ffs(m0) - 1; m0 &= m0 - 1;
                        const float* w = wk + ci * 26;
                        acc[0][0] = __fadd_rn(acc[0][0], w[0]);
                        acc[1][0] = __fadd_rn(acc[1][0], w[1]);
                        acc[2][0] = __fadd_rn(acc[2][0], w[2]);
                        acc[3][0] = __fadd_rn(acc[3][0], w[3]);
                        acc[4][0] = __fadd_rn(acc[4][0], w[4]);
                    }
                    while (m1) {
                        int ci = __ffs(m1) - 1; m1 &= m1 - 1;
                        const float* w = wk + ci * 26;
                        acc[0][1] = __fadd_rn(acc[0][1], w[0]);
                        acc[1][1] = __fadd_rn(acc[1][1], w[1]);
                        acc[2][1] = __fadd_rn(acc[2][1], w[2]);
                        acc[3][1] = __fadd_rn(acc[3][1], w[3]);
                        acc[4][1] = __fadd_rn(acc[4][1], w[4]);
                    }
                    while (m2w) {
                        int ci = __ffs(m2w) - 1; m2w &= m2w - 1;
                        const float* w = wk + ci * 26;
                        acc[0][2] = __fadd_rn(acc[0][2], w[0]);
                        acc[1][2] = __fadd_rn(acc[1][2], w[1]);
                        acc[2][2] = __fadd_rn(acc[2][2], w[2]);
                        acc[3][2] = __fadd_rn(acc[3][2], w[3]);
                        acc[4][2] = __fadd_rn(acc[4][2], w[4]);
                    }
                    while (m3) {
                        int ci = __ffs(m3) - 1; m3 &= m3 - 1;
                        const float* w = wk + ci * 26;
                        acc[0][3] = __fadd_rn(acc[0][3], w[0]);
                        acc[1][3] = __fadd_rn(acc[1][3], w[1]);
                        acc[2][3] = __fadd_rn(acc[2][3], w[2]);
                        acc[3][3] = __fadd_rn(acc[3][3], w[3]);
                        acc[4][3] = __fadd_rn(acc[4][3], w[4]);
                    }
                }
            }
#pragma unroll
            for (int u = 0; u < 5; u++) {
                int colocal = cog * 5 + u;
                int mb = colocal * 196;
                int i00 = r0 * 14 + c0;
                float m00 = m2[mb + i00]      + acc[u][0];
                float m01 = m2[mb + i00 + 1]  + acc[u][1];
                float m10 = m2[mb + i00 + 14] + acc[u][2];
                float m11 = m2[mb + i00 + 15] + acc[u][3];
                float f00 = (m00 > 1.f) ? 1.f : 0.f; m2[mb + i00]      = (m00 > 1.f) ? 0.f : m00;
                float f01 = (m01 > 1.f) ? 1.f : 0.f; m2[mb + i00 + 1]  = (m01 > 1.f) ? 0.f : m01;
                float f10 = (m10 > 1.f) ? 1.f : 0.f; m2[mb + i00 + 14] = (m10 > 1.f) ? 0.f : m10;
                float f11 = (m11 > 1.f) ? 1.f : 0.f; m2[mb + i00 + 15] = (m11 > 1.f) ? 0.f : m11;
                int pi = colocal * 49 + q;
                float ms = m2s[pi] + 0.25f * (f00 + f01 + f10 + f11);
                if (ms > 0.75f) {
                    m2s[pi] = 0.f;
                    int bit = colocal * 49 + q;
                    atomicOr(&smask[bit >> 5], 1u << (bit & 31));
                } else {
                    m2s[pi] = ms;
                }
            }
        }
        __syncthreads();
        if (t < 39) g_op2m_all[tt][b][cb][t] = smask[t];
        __syncthreads();
    }
}

// ---------------- fc0, ALL steps: mf0/tf0 in registers; sparse gather per step ----------------
__global__ __launch_bounds__(256) void k_fc0_all() {
    int b = blockIdx.x;
    __shared__ uint32_t mw[78];
    __shared__ int pfx[79];
    __shared__ uint16_t klist[2450];
    int t = threadIdx.x;
    float mf0 = 0.f, tf0 = 0.f;

    for (int tt = 0; tt < NSTEPS; tt++) {
        if (t < 39)            mw[t] = g_op2m_all[tt][b][0][t];
        else if (t < 78)       mw[t] = g_op2m_all[tt][b][1][t - 39];
        __syncthreads();
        if (t == 0) {
            int s = 0;
            for (int w = 0; w < 78; w++) { pfx[w] = s; s += __popc(mw[w]); }
            pfx[78] = s;
        }
        __syncthreads();
        if (t < 78) {
            uint32_t m = mw[t];
            int base = (t < 39 ? 0 : 1225) + (t < 39 ? t : t - 39) * 32;
            int o = pfx[t];
            while (m) { int j = __ffs(m) - 1; m &= m - 1; klist[o++] = (uint16_t)(base + j); }
        }
        __syncthreads();
        int nb = pfx[78];
        if (t < 200) {
            const float* col = g_wf0T + t;
            float acc = 0.f;
            int i = 0;
            for (; i + 8 <= nb; i += 8) {
                float v0 = __ldg(&col[(int)klist[i]     * 200]);
                float v1 = __ldg(&col[(int)klist[i + 1] * 200]);
                float v2 = __ldg(&col[(int)klist[i + 2] * 200]);
                float v3 = __ldg(&col[(int)klist[i + 3] * 200]);
                float v4 = __ldg(&col[(int)klist[i + 4] * 200]);
                float v5 = __ldg(&col[(int)klist[i + 5] * 200]);
                float v6 = __ldg(&col[(int)klist[i + 6] * 200]);
                float v7 = __ldg(&col[(int)klist[i + 7] * 200]);
                acc = __fadd_rn(acc, v0); acc = __fadd_rn(acc, v1);
                acc = __fadd_rn(acc, v2); acc = __fadd_rn(acc, v3);
                acc = __fadd_rn(acc, v4); acc = __fadd_rn(acc, v5);
                acc = __fadd_rn(acc, v6); acc = __fadd_rn(acc, v7);
            }
            for (; i < nb; i++) acc = __fadd_rn(acc, __ldg(&col[(int)klist[i] * 200]));
            float m = mf0 + acc;
            float o = (m > 1.f) ? 1.f : 0.f;
            mf0 = (m > 1.f) ? 0.f : m;
            tf0 += o;
        }
        __syncthreads();   // mw/klist reused next step
    }
    if (t < 200) g_tf0[b * 200 + t] = tf0;
}

// ---------------- final readout: out = (Tf0 @ wf1^T) / 100 ----------------
__global__ void k_final(const float* __restrict__ wf1, float* __restrict__ out) {
    int i = blockIdx.x * blockDim.x + threadIdx.x;
    if (i >= BN * 10) return;
    int b = i / 10, j = i % 10;
    const float* tf = &g_tf0[b * 200];
    const float* w  = &wf1[j * 200];
    float s = 0.f;
#pragma unroll 8
    for (int n = 0; n < 200; n++) s = __fmaf_rn(tf[n], w[n], s);
    out[i] = s / 100.0f;
}

// ---------------- launch ----------------
extern "C" void kernel_launch(void* const* d_in, const int* in_sizes, int n_in,
                              void* d_out, int out_size) {
    const float* in  = (const float*)d_in[0];
    const float* w1  = (const float*)d_in[1];
    const float* w2  = (const float*)d_in[2];
    const float* wf0 = (const float*)d_in[3];
    const float* wf1 = (const float*)d_in[4];
    float* out = (float*)d_out;

    cudaFuncSetAttribute(k_conv1_all, cudaFuncAttributeMaxDynamicSharedMemorySize, C1_SMEM);
    cudaFuncSetAttribute(k_conv2_all, cudaFuncAttributeMaxDynamicSharedMemorySize, C2_SMEM);

    k_prep<<<(2 * 500 * 26 + 2450 * 200 + 255) / 256, 256>>>(w2, wf0);
    k_conv1_all<<<BN, 224, C1_SMEM>>>(in, w1);
    k_conv2_all<<<dim3(BN, 2), 256, C2_SMEM>>>();
    k_fc0_all<<<BN, 256>>>();
    k_final<<<(BN * 10 + 255) / 256, 256>>>(wf1, out);
}

// round 15
// speedup vs baseline: 1.2029x; 1.2029x over previous
#include <cuda_runtime.h>
#include <cstdint>

#define BN 512
#define NSTEPS 100

// ---------------- persistent device state (allocation-free scratch) ----------------
__device__ uint32_t g_opm_all [NSTEPS][BN * 196];   // pool1 spike masks per step (bit ci)
__device__ uint32_t g_op2m_all[NSTEPS][BN][2][40];  // pool2 spike masks per step (k=cb*1225+w*32+j)
__device__ float    g_tf0 [BN * 200];               // fc0 total spike count (ONLY output that matters)
__device__ float    g_w2t [2 * 500 * 26];           // conv2 weights pre-transposed [cb][kk*20+ci][ch pad26]
__device__ float    g_wf0T[2450 * 200];             // wf0 transposed [k][n]

// ---------------- Threefry-2x32, 20 rounds (matches JAX exactly) ----------------
__host__ __device__ __forceinline__ void tf2x32(uint32_t k0, uint32_t k1,
                                                uint32_t x0, uint32_t x1,
                                                uint32_t& o0, uint32_t& o1) {
    uint32_t k2 = k0 ^ k1 ^ 0x1BD11BDAu;
    x0 += k0; x1 += k1;
#define TFR(r) { x0 += x1; x1 = (x1 << (r)) | (x1 >> (32 - (r))); x1 ^= x0; }
    TFR(13) TFR(15) TFR(26) TFR(6)   x0 += k1; x1 += k2 + 1u;
    TFR(17) TFR(29) TFR(16) TFR(24)  x0 += k2; x1 += k0 + 2u;
    TFR(13) TFR(15) TFR(26) TFR(6)   x0 += k0; x1 += k1 + 3u;
    TFR(17) TFR(29) TFR(16) TFR(24)  x0 += k1; x1 += k2 + 4u;
    TFR(13) TFR(15) TFR(26) TFR(6)   x0 += k2; x1 += k0 + 5u;
#undef TFR
    o0 = x0; o1 = x1;
}

// ---------------- one-time prep: transpose w2 and wf0 ----------------
__global__ void k_prep(const float* __restrict__ w2, const float* __restrict__ wf0) {
    int i = blockIdx.x * blockDim.x + threadIdx.x;
    if (i < 2 * 500 * 26) {
        int ch = i % 26, rem = i / 26, kkci = rem % 500, cb = rem / 500;
        int kk = kkci / 20, ci = kkci % 20;
        g_w2t[i] = (ch < 25) ? w2[(cb * 25 + ch) * 500 + ci * 25 + kk] : 0.f;
    }
    int j = i - 2 * 500 * 26;
    if (j >= 0 && j < 2450 * 200) {
        int n = j % 200, k = j / 200;
        g_wf0T[j] = wf0[n * 2450 + k];
    }
}

// ---------------- conv1, ALL steps: m1 in smem, m1s in REGISTERS ----------------
// block = image, 224 threads (196 compute). Per-step math byte-identical to round 13.
#define C1_SMEM ((15680 + 1024 + 784 + 500) * 4)   // m1, sin, img, sw  (71952 B)
__global__ __launch_bounds__(224, 3) void k_conv1_all(const float* __restrict__ in,
                                                      const float* __restrict__ w1) {
    extern __shared__ float dynf[];
    float* m1   = dynf;                  // 20*784
    float* sin_ = dynf + 15680;          // 32*32 padded spikes
    float* img  = dynf + 16704;          // 784 raw input
    float* sw   = dynf + 17488;          // 20*25 weights
    int b = blockIdx.x;
    int t = threadIdx.x;
    for (int i = t; i < 15680; i += 224) m1[i] = 0.f;
    for (int i = t; i < 1024;  i += 224) sin_[i] = 0.f;
    for (int i = t; i < 784;   i += 224) img[i] = in[b * 784 + i];
    for (int i = t; i < 500;   i += 224) sw[i] = w1[i];
    __syncthreads();

    float m1s_r[20];
#pragma unroll
    for (int ch = 0; ch < 20; ch++) m1s_r[ch] = 0.f;

    for (int tt = 0; tt < NSTEPS; tt++) {
        uint32_t kk0, kk1;
        tf2x32(0u, 42u, 0u, (uint32_t)tt, kk0, kk1);
        for (int i = t; i < 784; i += 224) {
            uint32_t o0, o1;
            tf2x32(kk0, kk1, 0u, (uint32_t)(b * 784 + i), o0, o1);
            uint32_t bits = o0 ^ o1;
            float u = __uint_as_float((bits >> 9) | 0x3f800000u) - 1.0f;
            float v = img[i];
            float sgn = (v > 0.f) ? 1.f : ((v < 0.f) ? -1.f : 0.f);
            sin_[(2 + i / 28) * 32 + 2 + i % 28] = (fabsf(v) * 0.5f > u) ? sgn : 0.f;
        }
        __syncthreads();

        if (t < 196) {
            int py = t / 14, px = t % 14;
            int r0 = 2 * py, c0 = 2 * px;
            float p[6][6];
#pragma unroll
            for (int r = 0; r < 6; r++)
#pragma unroll
                for (int c = 0; c < 6; c++) p[r][c] = sin_[(r0 + r) * 32 + c0 + c];

            uint32_t mask = 0u;
#pragma unroll
            for (int ch = 0; ch < 20; ch++) {
                const float* w = &sw[ch * 25];
                float a00 = 0.f, a01 = 0.f, a10 = 0.f, a11 = 0.f;
#pragma unroll
                for (int ky = 0; ky < 5; ky++)
#pragma unroll
                    for (int kx = 0; kx < 5; kx++) {
                        float wv = w[ky * 5 + kx];
                        a00 = __fmaf_rn(p[ky][kx],         wv, a00);
                        a01 = __fmaf_rn(p[ky][kx + 1],     wv, a01);
                        a10 = __fmaf_rn(p[ky + 1][kx],     wv, a10);
                        a11 = __fmaf_rn(p[ky + 1][kx + 1], wv, a11);
                    }
                int mb = ch * 784;
                int i00 = r0 * 28 + c0;
                float m00 = m1[mb + i00]      + a00;
                float m01 = m1[mb + i00 + 1]  + a01;
                float m10 = m1[mb + i00 + 28] + a10;
                float m11 = m1[mb + i00 + 29] + a11;
                float f00 = (m00 > 1.f) ? 1.f : 0.f; m1[mb + i00]      = (m00 > 1.f) ? 0.f : m00;
                float f01 = (m01 > 1.f) ? 1.f : 0.f; m1[mb + i00 + 1]  = (m01 > 1.f) ? 0.f : m01;
                float f10 = (m10 > 1.f) ? 1.f : 0.f; m1[mb + i00 + 28] = (m10 > 1.f) ? 0.f : m10;
                float f11 = (m11 > 1.f) ? 1.f : 0.f; m1[mb + i00 + 29] = (m11 > 1.f) ? 0.f : m11;
                float ms = m1s_r[ch] + 0.25f * (f00 + f01 + f10 + f11);
                if (ms > 0.75f) { mask |= (1u << ch); m1s_r[ch] = 0.f; }
                else            { m1s_r[ch] = ms; }
            }
            g_opm_all[tt][b * 196 + t] = mask;
        }
        __syncthreads();
    }
}

// ---------------- conv2, ALL steps: weights+m2s in smem, m2 in REGISTERS ----------------
// block = (image, cb); 256 threads = 5 cogs x 49 positions, 5 ch/thread.
#define C2_SMEM ((13000 + 1225 + 2 * 324 + 2 * 40) * 4)   // 59812 B
__global__ __launch_bounds__(256, 3) void k_conv2_all() {
    extern __shared__ float dynf[];
    float*    swt    = dynf;                            // 25*500 weights (kk*520+ci*26+ch)
    float*    m2s    = dynf + 13000;                    // 25*49 pool membranes
    uint32_t* smA    = (uint32_t*)(dynf + 14225);       // 2 x 324 mask buffers
    uint32_t* smaskA = (uint32_t*)(dynf + 14225 + 648); // 2 x 40 output masks
    int b  = blockIdx.x;
    int cb = blockIdx.y;
    int t = threadIdx.x;
    {
        const float4* src = (const float4*)(g_w2t + cb * 13000);
        float4* dst = (float4*)swt;
        for (int i = t; i < 3250; i += 256) dst[i] = src[i];
    }
    for (int i = t; i < 1225; i += 256) m2s[i] = 0.f;
    for (int i = t; i < 324; i += 256) {
        int rr = i / 18 - 2, cc = i % 18 - 2;
        smA[i] = (rr >= 0 && rr < 14 && cc >= 0 && cc < 14) ? g_opm_all[0][b * 196 + rr * 14 + cc] : 0u;
    }
    if (t < 40) smaskA[t] = 0u;
    __syncthreads();

    // per-thread conv2 membranes (thread-owned: 5 channels x 4 positions)
    float m2r[5][4];
#pragma unroll
    for (int u = 0; u < 5; u++)
#pragma unroll
        for (int v = 0; v < 4; v++) m2r[u][v] = 0.f;

    for (int tt = 0; tt < NSTEPS; tt++) {
        int cur = tt & 1;
        uint32_t* sm    = smA + cur * 324;
        uint32_t* smask = smaskA + cur * 40;
        if (tt + 1 < NSTEPS) {
            uint32_t* smn = smA + (1 - cur) * 324;
            for (int i = t; i < 324; i += 256) {
                int rr = i / 18 - 2, cc = i % 18 - 2;
                smn[i] = (rr >= 0 && rr < 14 && cc >= 0 && cc < 14) ? g_opm_all[tt + 1][b * 196 + rr * 14 + cc] : 0u;
            }
            if (t < 40) smaskA[(1 - cur) * 40 + t] = 0u;
        }

        if (t < 245) {
            int cog = t / 49, q = t % 49;
            int py = q / 7, px = q % 7;
            int r0 = 2 * py, c0 = 2 * px;
            float acc[5][4] = {};
#pragma unroll 1
            for (int ky = 0; ky < 5; ky++) {
                const uint32_t* mr0 = &sm[(r0 + ky) * 18 + c0];
                const uint32_t* mr1 = mr0 + 18;
#pragma unroll 1
                for (int kx = 0; kx < 5; kx++) {
                    uint32_t m0 = mr0[kx], m1 = mr0[kx + 1];
                    uint32_t m2w = mr1[kx], m3 = mr1[kx + 1];
                    const float* wk = &swt[(ky * 5 + kx) * 20 * 26 + cog * 5];
                    while (m0) {
                        int ci = __ffs(m0) - 1; m0 &= m0 - 1;
                        const float* w = wk + ci * 26;
                        acc[0][0] = __fadd_rn(acc[0][0], w[0]);
                        acc[1][0] = __fadd_rn(acc[1][0], w[1]);
                        acc[2][0] = __fadd_rn(acc[2][0], w[2]);
                        acc[3][0] = __fadd_rn(acc[3][0], w[3]);
                        acc[4][0] = __fadd_rn(acc[4][0], w[4]);
                    }
                    while (m1) {
                        int ci = __ffs(m1) - 1; m1 &= m1 - 1;
                        const float* w = wk + ci * 26;
                        acc[0][1] = __fadd_rn(acc[0][1], w[0]);
                        acc[1][1] = __fadd_rn(acc[1][1], w[1]);
                        acc[2][1] = __fadd_rn(acc[2][1], w[2]);
                        acc[3][1] = __fadd_rn(acc[3][1], w[3]);
                        acc[4][1] = __fadd_rn(acc[4][1], w[4]);
                    }
                    while (m2w) {
                        int ci = __ffs(m2w) - 1; m2w &= m2w - 1;
                        const float* w = wk + ci * 26;
                        acc[0][2] = __fadd_rn(acc[0][2], w[0]);
                        acc[1][2] = __fadd_rn(acc[1][2], w[1]);
                        acc[2][2] = __fadd_rn(acc[2][2], w[2]);
                        acc[3][2] = __fadd_rn(acc[3][2], w[3]);
                        acc[4][2] = __fadd_rn(acc[4][2], w[4]);
                    }
                    while (m3) {
                        int ci = __ffs(m3) - 1; m3 &= m3 - 1;
                        const float* w = wk + ci * 26;
                        acc[0][3] = __fadd_rn(acc[0][3], w[0]);
                        acc[1][3] = __fadd_rn(acc[1][3], w[1]);
                        acc[2][3] = __fadd_rn(acc[2][3], w[2]);
                        acc[3][3] = __fadd_rn(acc[3][3], w[3]);
                        acc[4][3] = __fadd_rn(acc[4][3], w[4]);
                    }
                }
            }
#pragma unroll
            for (int u = 0; u < 5; u++) {
                int colocal = cog * 5 + u;
                float m00 = m2r[u][0] + acc[u][0];
                float m01 = m2r[u][1] + acc[u][1];
                float m10 = m2r[u][2] + acc[u][2];
                float m11 = m2r[u][3] + acc[u][3];
                float f00 = (m00 > 1.f) ? 1.f : 0.f; m2r[u][0] = (m00 > 1.f) ? 0.f : m00;
                float f01 = (m01 > 1.f) ? 1.f : 0.f; m2r[u][1] = (m01 > 1.f) ? 0.f : m01;
                float f10 = (m10 > 1.f) ? 1.f : 0.f; m2r[u][2] = (m10 > 1.f) ? 0.f : m10;
                float f11 = (m11 > 1.f) ? 1.f : 0.f; m2r[u][3] = (m11 > 1.f) ? 0.f : m11;
                int pi = colocal * 49 + q;
                float ms = m2s[pi] + 0.25f * (f00 + f01 + f10 + f11);
                if (ms > 0.75f) {
                    m2s[pi] = 0.f;
                    int bit = colocal * 49 + q;
                    atomicOr(&smask[bit >> 5], 1u << (bit & 31));
                } else {
                    m2s[pi] = ms;
                }
            }
        }
        __syncthreads();
        if (t < 39) g_op2m_all[tt][b][cb][t] = smask[t];
        __syncthreads();
    }
}

// ---------------- fc0, ALL steps: mf0/tf0 in registers; sparse gather per step ----------------
__global__ __launch_bounds__(256) void k_fc0_all() {
    int b = blockIdx.x;
    __shared__ uint32_t mw[78];
    __shared__ int pfx[79];
    __shared__ uint16_t klist[2450];
    int t = threadIdx.x;
    float mf0 = 0.f, tf0 = 0.f;

    for (int tt = 0; tt < NSTEPS; tt++) {
        if (t < 39)            mw[t] = g_op2m_all[tt][b][0][t];
        else if (t < 78)       mw[t] = g_op2m_all[tt][b][1][t - 39];
        __syncthreads();
        if (t == 0) {
            int s = 0;
            for (int w = 0; w < 78; w++) { pfx[w] = s; s += __popc(mw[w]); }
            pfx[78] = s;
        }
        __syncthreads();
        if (t < 78) {
            uint32_t m = mw[t];
            int base_k = (t < 39 ? 0 : 1225) + (t < 39 ? t : t - 39) * 32;
            int o = pfx[t];
            while (m) { int j = __ffs(m) - 1; m &= m - 1; klist[o++] = (uint16_t)(base_k + j); }
        }
        __syncthreads();
        int nb = pfx[78];
        if (t < 200) {
            const float* col = g_wf0T + t;
            float acc = 0.f;
            int i = 0;
            for (; i + 8 <= nb; i += 8) {
                float v0 = __ldg(&col[(int)klist[i]     * 200]);
                float v1 = __ldg(&col[(int)klist[i + 1] * 200]);
                float v2 = __ldg(&col[(int)klist[i + 2] * 200]);
                float v3 = __ldg(&col[(int)klist[i + 3] * 200]);
                float v4 = __ldg(&col[(int)klist[i + 4] * 200]);
                float v5 = __ldg(&col[(int)klist[i + 5] * 200]);
                float v6 = __ldg(&col[(int)klist[i + 6] * 200]);
                float v7 = __ldg(&col[(int)klist[i + 7] * 200]);
                acc = __fadd_rn(acc, v0); acc = __fadd_rn(acc, v1);
                acc = __fadd_rn(acc, v2); acc = __fadd_rn(acc, v3);
                acc = __fadd_rn(acc, v4); acc = __fadd_rn(acc, v5);
                acc = __fadd_rn(acc, v6); acc = __fadd_rn(acc, v7);
            }
            for (; i < nb; i++) acc = __fadd_rn(acc, __ldg(&col[(int)klist[i] * 200]));
            float m = mf0 + acc;
            float o = (m > 1.f) ? 1.f : 0.f;
            mf0 = (m > 1.f) ? 0.f : m;
            tf0 += o;
        }
        __syncthreads();
    }
    if (t < 200) g_tf0[b * 200 + t] = tf0;
}

// ---------------- final readout: out = (Tf0 @ wf1^T) / 100 ----------------
__global__ void k_final(const float* __restrict__ wf1, float* __restrict__ out) {
    int i = blockIdx.x * blockDim.x + threadIdx.x;
    if (i >= BN * 10) return;
    int b = i / 10, j = i % 10;
    const float* tf = &g_tf0[b * 200];
    const float* w  = &wf1[j * 200];
    float s = 0.f;
#pragma unroll 8
    for (int n = 0; n < 200; n++) s = __fmaf_rn(tf[n], w[n], s);
    out[i] = s / 100.0f;
}

// ---------------- launch (single default stream — no stream/event objects) ----------------
extern "C" void kernel_launch(void* const* d_in, const int* in_sizes, int n_in,
                              void* d_out, int out_size) {
    const float* in  = (const float*)d_in[0];
    const float* w1  = (const float*)d_in[1];
    const float* w2  = (const float*)d_in[2];
    const float* wf0 = (const float*)d_in[3];
    const float* wf1 = (const float*)d_in[4];
    float* out = (float*)d_out;

    cudaFuncSetAttribute(k_conv1_all, cudaFuncAttributeMaxDynamicSharedMemorySize, C1_SMEM);
    cudaFuncSetAttribute(k_conv2_all, cudaFuncAttributeMaxDynamicSharedMemorySize, C2_SMEM);

    k_prep<<<(2 * 500 * 26 + 2450 * 200 + 255) / 256, 256>>>(w2, wf0);
    k_conv1_all<<<BN, 224, C1_SMEM>>>(in, w1);
    k_conv2_all<<<dim3(BN, 2), 256, C2_SMEM>>>();
    k_fc0_all<<<BN, 256>>>();
    k_final<<<(BN * 10 + 255) / 256, 256>>>(wf1, out);
}